// round 11
// baseline (speedup 1.0000x reference)
#include <cuda_runtime.h>
#include <cuda_bf16.h>
#include <cstdint>
#include <cstddef>

#define B_ 4096
#define T_ 80
#define V_ 10000
#define E_ 100
#define U_ 1024

#define KTOT 1152            // 1024 (Wh) + 128 (Wx padded from 100)
#define EPAD 128             // padded embedding width
#define NCHUNK 36            // KTOT / 32
#define MT 128
#define NT 128
#define KC 32
#define NSTAGE 2
#define NTHREADS 256
#define LDAB 40              // row stride in bf16 elements (80 B): conflict-free ldmatrix

// byte sizes
#define ROWB (LDAB * 2)                  // 80 B per row
#define A_PLANE_B (MT * ROWB)            // 10240
#define A_STAGE_B (2 * A_PLANE_B)        // 20480 (hi + lo)
#define B_PLANE_B (NT * ROWB)            // 10240
#define B_STAGE_B (2 * B_PLANE_B)        // 20480
#define SM_A_OFF   0
#define SM_B_OFF   (NSTAGE * A_STAGE_B)                 // 40960
#define SM_IDX_OFF (SM_B_OFF + NSTAGE * B_STAGE_B)      // 81920
#define SMEM_TOTAL (SM_IDX_OFF + MT * 4)                // 82432

// ---- device scratch (allocation-free) ----
__device__ __align__(256) __nv_bfloat16 g_h_hi[2][(size_t)B_ * U_];
__device__ __align__(256) __nv_bfloat16 g_h_lo[2][(size_t)B_ * U_];
__device__ __align__(256) __nv_bfloat16 g_Bth[(size_t)U_ * KTOT];   // [n][k] hi
__device__ __align__(256) __nv_bfloat16 g_Btl[(size_t)U_ * KTOT];   // [n][k] lo
__device__ __align__(256) __nv_bfloat16 g_emb_hi[(size_t)V_ * EPAD];
__device__ __align__(256) __nv_bfloat16 g_emb_lo[(size_t)V_ * EPAD];

static __device__ __forceinline__ uint32_t smem_u32(const void* p) {
    uint32_t a;
    asm("{ .reg .u64 t; cvta.to.shared.u64 t, %1; cvt.u32.u64 %0, t; }" : "=r"(a) : "l"(p));
    return a;
}
static __device__ __forceinline__ void cp_async16(uint32_t s, const void* g) {
    asm volatile("cp.async.cg.shared.global [%0], [%1], 16;" :: "r"(s), "l"(g));
}
static __device__ __forceinline__ void split_bf16(float v, __nv_bfloat16& hi, __nv_bfloat16& lo) {
    hi = __float2bfloat16(v);
    lo = __float2bfloat16(v - __bfloat162float(hi));
}
static __device__ __forceinline__ void ldsm4(uint32_t* r, uint32_t addr) {
    asm volatile("ldmatrix.sync.aligned.m8n8.x4.shared.b16 {%0,%1,%2,%3}, [%4];"
                 : "=r"(r[0]), "=r"(r[1]), "=r"(r[2]), "=r"(r[3]) : "r"(addr));
}
static __device__ __forceinline__ void mma_bf16(float* c, const uint32_t* a,
                                                uint32_t b0, uint32_t b1) {
    asm volatile("mma.sync.aligned.m16n8k16.row.col.f32.bf16.bf16.f32 "
                 "{%0,%1,%2,%3}, {%4,%5,%6,%7}, {%8,%9}, {%0,%1,%2,%3};"
                 : "+f"(c[0]), "+f"(c[1]), "+f"(c[2]), "+f"(c[3])
                 : "r"(a[0]), "r"(a[1]), "r"(a[2]), "r"(a[3]), "r"(b0), "r"(b1));
}

// ---------------- prep kernels ----------------
__global__ void prep_bt_kernel(const float* __restrict__ Wh, const float* __restrict__ Wx) {
    int idx = blockIdx.x * 256 + threadIdx.x;
    if (idx >= U_ * KTOT) return;
    int n = idx / KTOT;
    int k = idx - n * KTOT;
    float v = 0.0f;
    if (k < U_)            v = Wh[(size_t)k * U_ + n];
    else if (k < U_ + E_)  v = Wx[(size_t)(k - U_) * U_ + n];
    __nv_bfloat16 hi, lo; split_bf16(v, hi, lo);
    g_Bth[idx] = hi; g_Btl[idx] = lo;
}
__global__ void prep_emb_kernel(const float* __restrict__ emb) {
    int idx = blockIdx.x * 256 + threadIdx.x;
    if (idx >= V_ * EPAD) return;
    int tok = idx >> 7;
    int k = idx & (EPAD - 1);
    float v = (k < E_) ? emb[(size_t)tok * E_ + k] : 0.0f;
    __nv_bfloat16 hi, lo; split_bf16(v, hi, lo);
    g_emb_hi[idx] = hi; g_emb_lo[idx] = lo;
}
__global__ void zero_h_kernel() {
    size_t i = (size_t)blockIdx.x * blockDim.x + threadIdx.x;
    if (i < (size_t)B_ * U_) {
        g_h_hi[0][i] = __float2bfloat16(0.0f);
        g_h_lo[0][i] = __float2bfloat16(0.0f);
    }
}

// ---------------- recurrence step: raw mma.m16n8k16 bf16, 3-MMA split ----------------
// Grid: (U_/NT = 8, B_/MT = 32) = 256 CTAs, 256 threads (8 warps, 4x2 -> 32x64 tiles).
// 2 CTAs/SM -> 16 warps/SM = 4 warps/SMSP for tensor-pipe latency hiding.
// R9-proven pipeline: wait_group 1, two barriers, issue(c+2) after compute.
__global__ __launch_bounds__(NTHREADS, 2)
void rnn_step_bf16(const int* __restrict__ inputs, const float* __restrict__ bvec, int t)
{
    extern __shared__ char smem[];
    int* sIdx = (int*)(smem + SM_IDX_OFF);
    const uint32_t sbase = smem_u32(smem);

    const int tid = threadIdx.x;
    const int wid = tid >> 5;
    const int lane = tid & 31;
    const int warp_m = wid & 3;       // 4 m-tiles of 32
    const int warp_n = wid >> 2;      // 2 n-tiles of 64
    const int n0 = blockIdx.x * NT;
    const int m0 = blockIdx.y * MT;

    const __nv_bfloat16* __restrict__ hh = g_h_hi[t & 1];
    const __nv_bfloat16* __restrict__ hl = g_h_lo[t & 1];
    __nv_bfloat16* __restrict__ nh = g_h_hi[(t & 1) ^ 1];
    __nv_bfloat16* __restrict__ nl = g_h_lo[(t & 1) ^ 1];

    if (tid < MT) sIdx[tid] = inputs[(size_t)(m0 + tid) * T_ + t];
    __syncthreads();

    float acc[2][8][4];
#pragma unroll
    for (int i = 0; i < 2; i++)
#pragma unroll
        for (int j = 0; j < 8; j++)
#pragma unroll
            for (int e = 0; e < 4; e++) acc[i][j][e] = 0.0f;

    // ldmatrix lane address components
    const int a_r = lane & 15;                      // A row within 16
    const int a_c = (lane >> 4) * 16;               // A byte offset (k half)
    const int b_r = (lane & 7) + ((lane >> 4) << 3);// B n-row within 16
    const int b_c = ((lane >> 3) & 1) * 16;         // B byte offset (k half)

    auto issue = [&](int c) {
        const int s = c % NSTAGE;
        const uint32_t aHiB = sbase + SM_A_OFF + (uint32_t)(s * A_STAGE_B);
        const uint32_t aLoB = aHiB + A_PLANE_B;
        if (c < 32) {
            const __nv_bfloat16* sh = hh + (size_t)m0 * U_ + c * KC;
            const __nv_bfloat16* sl = hl + (size_t)m0 * U_ + c * KC;
#pragma unroll
            for (int r = 0; r < 2; r++) {
                int idx = r * NTHREADS + tid;
                int row = idx >> 2, sc = idx & 3;
                uint32_t off = (uint32_t)(row * ROWB + sc * 16);
                cp_async16(aHiB + off, sh + (size_t)row * U_ + sc * 8);
                cp_async16(aLoB + off, sl + (size_t)row * U_ + sc * 8);
            }
        } else {
            const int kb = (c - 32) * KC;
#pragma unroll
            for (int r = 0; r < 2; r++) {
                int idx = r * NTHREADS + tid;
                int row = idx >> 2, sc = idx & 3;
                uint32_t off = (uint32_t)(row * ROWB + sc * 16);
                size_t g = (size_t)sIdx[row] * EPAD + kb + sc * 8;
                cp_async16(aHiB + off, g_emb_hi + g);
                cp_async16(aLoB + off, g_emb_lo + g);
            }
        }
        const uint32_t bHiB = sbase + SM_B_OFF + (uint32_t)(s * B_STAGE_B);
        const uint32_t bLoB = bHiB + B_PLANE_B;
        const __nv_bfloat16* bh = g_Bth + (size_t)n0 * KTOT + c * KC;
        const __nv_bfloat16* bl = g_Btl + (size_t)n0 * KTOT + c * KC;
#pragma unroll
        for (int r = 0; r < 2; r++) {
            int idx = r * NTHREADS + tid;
            int row = idx >> 2, sc = idx & 3;
            uint32_t off = (uint32_t)(row * ROWB + sc * 16);
            cp_async16(bHiB + off, bh + (size_t)row * KTOT + sc * 8);
            cp_async16(bLoB + off, bl + (size_t)row * KTOT + sc * 8);
        }
        asm volatile("cp.async.commit_group;" ::: "memory");
    };

    issue(0); issue(1);

    for (int c = 0; c < NCHUNK; c++) {
        if (c < NCHUNK - 1) asm volatile("cp.async.wait_group 1;" ::: "memory");
        else                asm volatile("cp.async.wait_group 0;" ::: "memory");
        __syncthreads();

        const int s = c % NSTAGE;
        const uint32_t aBase = sbase + SM_A_OFF + (uint32_t)(s * A_STAGE_B)
                             + (uint32_t)(warp_m * 32 * ROWB);
        const uint32_t bBase = sbase + SM_B_OFF + (uint32_t)(s * B_STAGE_B)
                             + (uint32_t)(warp_n * 64 * ROWB);

#pragma unroll
        for (int k16 = 0; k16 < 2; k16++) {
            // Hold A fragments for this k16 (2 m-slabs of 16, hi+lo): 4 LDSM
            uint32_t ah[2][4], al[2][4];
#pragma unroll
            for (int i = 0; i < 2; i++) {
                uint32_t addr = aBase + (uint32_t)((i * 16 + a_r) * ROWB + k16 * 32 + a_c);
                ldsm4(ah[i], addr);
                ldsm4(al[i], addr + A_PLANE_B);
            }
            // Stream B with double buffer: prefetch B(jj+1) during jj's MMAs
            uint32_t bh[2][4], bl[2][4];
            {
                uint32_t baddr = bBase + (uint32_t)((b_r) * ROWB + k16 * 32 + b_c);
                ldsm4(bh[0], baddr);
                ldsm4(bl[0], baddr + B_PLANE_B);
            }
#pragma unroll
            for (int jj = 0; jj < 4; jj++) {
                const int cur = jj & 1;
                if (jj < 3) {
                    uint32_t baddr = bBase + (uint32_t)(((jj + 1) * 16 + b_r) * ROWB + k16 * 32 + b_c);
                    ldsm4(bh[cur ^ 1], baddr);
                    ldsm4(bl[cur ^ 1], baddr + B_PLANE_B);
                }
#pragma unroll
                for (int i = 0; i < 2; i++) {
                    mma_bf16(acc[i][2 * jj],     ah[i], bh[cur][0], bh[cur][1]);
                    mma_bf16(acc[i][2 * jj],     al[i], bh[cur][0], bh[cur][1]);
                    mma_bf16(acc[i][2 * jj],     ah[i], bl[cur][0], bl[cur][1]);
                    mma_bf16(acc[i][2 * jj + 1], ah[i], bh[cur][2], bh[cur][3]);
                    mma_bf16(acc[i][2 * jj + 1], al[i], bh[cur][2], bh[cur][3]);
                    mma_bf16(acc[i][2 * jj + 1], ah[i], bl[cur][2], bl[cur][3]);
                }
            }
        }
        __syncthreads();
        if (c + NSTAGE < NCHUNK) issue(c + NSTAGE);
    }

    // ---- epilogue: bias + tanh + bf16 hi/lo split + direct store from acc frags ----
    const int er = lane >> 2;
    const int ec = (lane & 3) * 2;
#pragma unroll
    for (int j = 0; j < 8; j++) {
        int gc = n0 + warp_n * 64 + j * 8 + ec;
        float bia0 = bvec[gc], bia1 = bvec[gc + 1];
#pragma unroll
        for (int i = 0; i < 2; i++) {
            int gr = m0 + warp_m * 32 + i * 16 + er;
            float t0 = tanhf(acc[i][j][0] + bia0);
            float t1 = tanhf(acc[i][j][1] + bia1);
            float t2 = tanhf(acc[i][j][2] + bia0);
            float t3 = tanhf(acc[i][j][3] + bia1);
            __nv_bfloat16 h0, l0, h1, l1;
            split_bf16(t0, h0, l0); split_bf16(t1, h1, l1);
            size_t o0 = (size_t)gr * U_ + gc;
            *(__nv_bfloat162*)(nh + o0) = __halves2bfloat162(h0, h1);
            *(__nv_bfloat162*)(nl + o0) = __halves2bfloat162(l0, l1);
            split_bf16(t2, h0, l0); split_bf16(t3, h1, l1);
            size_t o1 = (size_t)(gr + 8) * U_ + gc;
            *(__nv_bfloat162*)(nh + o1) = __halves2bfloat162(h0, h1);
            *(__nv_bfloat162*)(nl + o1) = __halves2bfloat162(l0, l1);
        }
    }
}

// out[row] = h_last[row, :] @ Wo + bo
__global__ void final_proj_kernel(const float* __restrict__ Wo,
                                  const float* __restrict__ bo,
                                  float* __restrict__ out)
{
    const __nv_bfloat16* hh = g_h_hi[0];   // T_=80 even -> final state in buffer 0
    const __nv_bfloat16* hl = g_h_lo[0];
    int row = blockIdx.x;
    int tid = threadIdx.x;     // 128 threads
    float s = 0.0f;
    size_t base = (size_t)row * U_;
#pragma unroll 4
    for (int i = tid; i < U_; i += 128) {
        float hv = __bfloat162float(hh[base + i]) + __bfloat162float(hl[base + i]);
        s += hv * Wo[i];
    }
#pragma unroll
    for (int o = 16; o > 0; o >>= 1) s += __shfl_down_sync(0xffffffffu, s, o);
    __shared__ float red[4];
    if ((tid & 31) == 0) red[tid >> 5] = s;
    __syncthreads();
    if (tid == 0) out[row] = red[0] + red[1] + red[2] + red[3] + bo[0];
}

extern "C" void kernel_launch(void* const* d_in, const int* in_sizes, int n_in,
                              void* d_out, int out_size)
{
    const int*   inputs = (const int*)  d_in[0];
    const float* emb    = (const float*)d_in[1];
    const float* Wx     = (const float*)d_in[2];
    const float* Wh     = (const float*)d_in[3];
    const float* b      = (const float*)d_in[4];
    const float* Wo     = (const float*)d_in[5];
    const float* bo     = (const float*)d_in[6];
    float* out = (float*)d_out;

    cudaFuncSetAttribute(rnn_step_bf16, cudaFuncAttributeMaxDynamicSharedMemorySize,
                         SMEM_TOTAL);

    // Prep: split/transposed/padded bf16 weights + embedding, h0 = 0
    prep_bt_kernel<<<(U_ * KTOT + 255) / 256, 256>>>(Wh, Wx);
    prep_emb_kernel<<<(V_ * EPAD + 255) / 256, 256>>>(emb);
    {
        size_t n = (size_t)B_ * U_;
        zero_h_kernel<<<(int)((n + 255) / 256), 256>>>();
    }

    // 80 recurrence steps (ping-pong hi/lo planes)
    dim3 grid(U_ / NT, B_ / MT);
    for (int t = 0; t < T_; t++) {
        rnn_step_bf16<<<grid, NTHREADS, SMEM_TOTAL>>>(inputs, b, t);
    }

    final_proj_kernel<<<B_, 128>>>(Wo, bo, out);
}

// round 12
// speedup vs baseline: 1.0382x; 1.0382x over previous
#include <cuda_runtime.h>
#include <cuda_bf16.h>
#include <cstdint>
#include <cstddef>

#define B_ 4096
#define T_ 80
#define V_ 10000
#define E_ 100
#define U_ 1024

#define KTOT 1152            // 1024 (Wh) + 128 (Wx padded from 100)
#define EPAD 128             // padded embedding width
#define NCHUNK 36            // KTOT / 32
#define MT 128
#define NT 128
#define KC 32
#define NSTAGE 2
#define NTHREADS 128
#define LDAB 40              // row stride in bf16 elements (80 B): conflict-free ldmatrix

// byte sizes
#define ROWB (LDAB * 2)                  // 80 B per row
#define A_PLANE_B (MT * ROWB)            // 10240
#define A_STAGE_B (2 * A_PLANE_B)        // 20480 (hi + lo)
#define B_PLANE_B (NT * ROWB)            // 10240
#define B_STAGE_B (2 * B_PLANE_B)        // 20480
#define SM_A_OFF   0
#define SM_B_OFF   (NSTAGE * A_STAGE_B)                 // 40960
#define SM_IDX_OFF (SM_B_OFF + NSTAGE * B_STAGE_B)      // 81920
#define SMEM_TOTAL (SM_IDX_OFF + MT * 4)                // 82432

// ---- device scratch (allocation-free) ----
__device__ __align__(256) __nv_bfloat16 g_h_hi[2][(size_t)B_ * U_];
__device__ __align__(256) __nv_bfloat16 g_h_lo[2][(size_t)B_ * U_];
__device__ __align__(256) __nv_bfloat16 g_Bth[(size_t)U_ * KTOT];   // [n][k] hi
__device__ __align__(256) __nv_bfloat16 g_Btl[(size_t)U_ * KTOT];   // [n][k] lo
__device__ __align__(256) __nv_bfloat16 g_emb_hi[(size_t)V_ * EPAD];
__device__ __align__(256) __nv_bfloat16 g_emb_lo[(size_t)V_ * EPAD];

static __device__ __forceinline__ uint32_t smem_u32(const void* p) {
    uint32_t a;
    asm("{ .reg .u64 t; cvta.to.shared.u64 t, %1; cvt.u32.u64 %0, t; }" : "=r"(a) : "l"(p));
    return a;
}
static __device__ __forceinline__ void cp_async16(uint32_t s, const void* g) {
    asm volatile("cp.async.cg.shared.global [%0], [%1], 16;" :: "r"(s), "l"(g));
}
static __device__ __forceinline__ void split_bf16(float v, __nv_bfloat16& hi, __nv_bfloat16& lo) {
    hi = __float2bfloat16(v);
    lo = __float2bfloat16(v - __bfloat162float(hi));
}
static __device__ __forceinline__ void ldsm4(uint32_t* r, uint32_t addr) {
    asm volatile("ldmatrix.sync.aligned.m8n8.x4.shared.b16 {%0,%1,%2,%3}, [%4];"
                 : "=r"(r[0]), "=r"(r[1]), "=r"(r[2]), "=r"(r[3]) : "r"(addr));
}
static __device__ __forceinline__ void mma_bf16(float* c, const uint32_t* a,
                                                uint32_t b0, uint32_t b1) {
    asm volatile("mma.sync.aligned.m16n8k16.row.col.f32.bf16.bf16.f32 "
                 "{%0,%1,%2,%3}, {%4,%5,%6,%7}, {%8,%9}, {%0,%1,%2,%3};"
                 : "+f"(c[0]), "+f"(c[1]), "+f"(c[2]), "+f"(c[3])
                 : "r"(a[0]), "r"(a[1]), "r"(a[2]), "r"(a[3]), "r"(b0), "r"(b1));
}

// ---------------- prep kernels ----------------
__global__ void prep_bt_kernel(const float* __restrict__ Wh, const float* __restrict__ Wx) {
    int idx = blockIdx.x * 256 + threadIdx.x;
    if (idx >= U_ * KTOT) return;
    int n = idx / KTOT;
    int k = idx - n * KTOT;
    float v = 0.0f;
    if (k < U_)            v = Wh[(size_t)k * U_ + n];
    else if (k < U_ + E_)  v = Wx[(size_t)(k - U_) * U_ + n];
    __nv_bfloat16 hi, lo; split_bf16(v, hi, lo);
    g_Bth[idx] = hi; g_Btl[idx] = lo;
}
__global__ void prep_emb_kernel(const float* __restrict__ emb) {
    int idx = blockIdx.x * 256 + threadIdx.x;
    if (idx >= V_ * EPAD) return;
    int tok = idx >> 7;
    int k = idx & (EPAD - 1);
    float v = (k < E_) ? emb[(size_t)tok * E_ + k] : 0.0f;
    __nv_bfloat16 hi, lo; split_bf16(v, hi, lo);
    g_emb_hi[idx] = hi; g_emb_lo[idx] = lo;
}
__global__ void zero_h_kernel() {
    size_t i = (size_t)blockIdx.x * blockDim.x + threadIdx.x;
    if (i < (size_t)B_ * U_) {
        g_h_hi[0][i] = __float2bfloat16(0.0f);
        g_h_lo[0][i] = __float2bfloat16(0.0f);
    }
}

// ---------------- recurrence step: raw mma.m16n8k16 bf16, 3-MMA split ----------------
// Grid: (U_/NT = 8, B_/MT = 32) = 256 CTAs, 128 threads (4 warps, 2x2 -> 64x64 tiles).
// 2 CTAs/SM. R9 pipeline (wait_group 1, two barriers, issue(c+2) after compute).
// NEW: term-major MMA passes (all hh, all lh, all hl) -> 32-wide acc independence.
__global__ __launch_bounds__(NTHREADS, 2)
void rnn_step_bf16(const int* __restrict__ inputs, const float* __restrict__ bvec, int t)
{
    extern __shared__ char smem[];
    int* sIdx = (int*)(smem + SM_IDX_OFF);
    const uint32_t sbase = smem_u32(smem);

    const int tid = threadIdx.x;
    const int wid = tid >> 5;
    const int lane = tid & 31;
    const int warp_m = wid & 1;       // 2 m-tiles of 64
    const int warp_n = wid >> 1;      // 2 n-tiles of 64
    const int n0 = blockIdx.x * NT;
    const int m0 = blockIdx.y * MT;

    const __nv_bfloat16* __restrict__ hh_g = g_h_hi[t & 1];
    const __nv_bfloat16* __restrict__ hl_g = g_h_lo[t & 1];
    __nv_bfloat16* __restrict__ nh = g_h_hi[(t & 1) ^ 1];
    __nv_bfloat16* __restrict__ nl = g_h_lo[(t & 1) ^ 1];

    sIdx[tid] = inputs[(size_t)(m0 + tid) * T_ + t];
    __syncthreads();

    float acc[4][8][4];
#pragma unroll
    for (int i = 0; i < 4; i++)
#pragma unroll
        for (int j = 0; j < 8; j++)
#pragma unroll
            for (int e = 0; e < 4; e++) acc[i][j][e] = 0.0f;

    // ldmatrix lane address components
    const int a_r = lane & 15;                      // A row within 16
    const int a_c = (lane >> 4) * 16;               // A byte offset (k half)
    const int b_r = (lane & 7) + ((lane >> 4) << 3);// B n-row within 16
    const int b_c = ((lane >> 3) & 1) * 16;         // B byte offset (k half)

    auto issue = [&](int c) {
        const int s = c % NSTAGE;
        const uint32_t aHiB = sbase + SM_A_OFF + (uint32_t)(s * A_STAGE_B);
        const uint32_t aLoB = aHiB + A_PLANE_B;
        if (c < 32) {
            const __nv_bfloat16* sh = hh_g + (size_t)m0 * U_ + c * KC;
            const __nv_bfloat16* sl = hl_g + (size_t)m0 * U_ + c * KC;
#pragma unroll
            for (int r = 0; r < 4; r++) {
                int idx = r * NTHREADS + tid;
                int row = idx >> 2, sc = idx & 3;
                uint32_t off = (uint32_t)(row * ROWB + sc * 16);
                cp_async16(aHiB + off, sh + (size_t)row * U_ + sc * 8);
                cp_async16(aLoB + off, sl + (size_t)row * U_ + sc * 8);
            }
        } else {
            const int kb = (c - 32) * KC;
#pragma unroll
            for (int r = 0; r < 4; r++) {
                int idx = r * NTHREADS + tid;
                int row = idx >> 2, sc = idx & 3;
                uint32_t off = (uint32_t)(row * ROWB + sc * 16);
                size_t g = (size_t)sIdx[row] * EPAD + kb + sc * 8;
                cp_async16(aHiB + off, g_emb_hi + g);
                cp_async16(aLoB + off, g_emb_lo + g);
            }
        }
        const uint32_t bHiB = sbase + SM_B_OFF + (uint32_t)(s * B_STAGE_B);
        const uint32_t bLoB = bHiB + B_PLANE_B;
        const __nv_bfloat16* bh_g = g_Bth + (size_t)n0 * KTOT + c * KC;
        const __nv_bfloat16* bl_g = g_Btl + (size_t)n0 * KTOT + c * KC;
#pragma unroll
        for (int r = 0; r < 4; r++) {
            int idx = r * NTHREADS + tid;
            int row = idx >> 2, sc = idx & 3;
            uint32_t off = (uint32_t)(row * ROWB + sc * 16);
            cp_async16(bHiB + off, bh_g + (size_t)row * KTOT + sc * 8);
            cp_async16(bLoB + off, bl_g + (size_t)row * KTOT + sc * 8);
        }
        asm volatile("cp.async.commit_group;" ::: "memory");
    };

    issue(0); issue(1);

    for (int c = 0; c < NCHUNK; c++) {
        if (c < NCHUNK - 1) asm volatile("cp.async.wait_group 1;" ::: "memory");
        else                asm volatile("cp.async.wait_group 0;" ::: "memory");
        __syncthreads();

        const int s = c % NSTAGE;
        const uint32_t aBase = sbase + SM_A_OFF + (uint32_t)(s * A_STAGE_B)
                             + (uint32_t)(warp_m * 64 * ROWB);
        const uint32_t bBase = sbase + SM_B_OFF + (uint32_t)(s * B_STAGE_B)
                             + (uint32_t)(warp_n * 64 * ROWB);

#pragma unroll
        for (int k16 = 0; k16 < 2; k16++) {
            // Load ALL fragments for this k16 (A hi/lo 4 m-tiles, B hi/lo 4 n-slabs)
            uint32_t ah[4][4], al[4][4], bh[4][4], bl[4][4];
#pragma unroll
            for (int i = 0; i < 4; i++) {
                uint32_t addr = aBase + (uint32_t)((i * 16 + a_r) * ROWB + k16 * 32 + a_c);
                ldsm4(ah[i], addr);
                ldsm4(al[i], addr + A_PLANE_B);
            }
#pragma unroll
            for (int jj = 0; jj < 4; jj++) {
                uint32_t baddr = bBase + (uint32_t)((jj * 16 + b_r) * ROWB + k16 * 32 + b_c);
                ldsm4(bh[jj], baddr);
                ldsm4(bl[jj], baddr + B_PLANE_B);
            }
            // Pass 1: hh into all 32 accumulators (independent)
#pragma unroll
            for (int i = 0; i < 4; i++)
#pragma unroll
                for (int jj = 0; jj < 4; jj++) {
                    mma_bf16(acc[i][2 * jj],     ah[i], bh[jj][0], bh[jj][1]);
                    mma_bf16(acc[i][2 * jj + 1], ah[i], bh[jj][2], bh[jj][3]);
                }
            // Pass 2: lo(A) x hi(B)
#pragma unroll
            for (int i = 0; i < 4; i++)
#pragma unroll
                for (int jj = 0; jj < 4; jj++) {
                    mma_bf16(acc[i][2 * jj],     al[i], bh[jj][0], bh[jj][1]);
                    mma_bf16(acc[i][2 * jj + 1], al[i], bh[jj][2], bh[jj][3]);
                }
            // Pass 3: hi(A) x lo(B)
#pragma unroll
            for (int i = 0; i < 4; i++)
#pragma unroll
                for (int jj = 0; jj < 4; jj++) {
                    mma_bf16(acc[i][2 * jj],     ah[i], bl[jj][0], bl[jj][1]);
                    mma_bf16(acc[i][2 * jj + 1], ah[i], bl[jj][2], bl[jj][3]);
                }
        }
        __syncthreads();
        if (c + NSTAGE < NCHUNK) issue(c + NSTAGE);
    }

    // ---- epilogue: bias + tanh + bf16 hi/lo split + direct store from acc frags ----
    const int er = lane >> 2;
    const int ec = (lane & 3) * 2;
#pragma unroll
    for (int j = 0; j < 8; j++) {
        int gc = n0 + warp_n * 64 + j * 8 + ec;
        float bia0 = bvec[gc], bia1 = bvec[gc + 1];
#pragma unroll
        for (int i = 0; i < 4; i++) {
            int gr = m0 + warp_m * 64 + i * 16 + er;
            float t0 = tanhf(acc[i][j][0] + bia0);
            float t1 = tanhf(acc[i][j][1] + bia1);
            float t2 = tanhf(acc[i][j][2] + bia0);
            float t3 = tanhf(acc[i][j][3] + bia1);
            __nv_bfloat16 h0, l0, h1, l1;
            split_bf16(t0, h0, l0); split_bf16(t1, h1, l1);
            size_t o0 = (size_t)gr * U_ + gc;
            *(__nv_bfloat162*)(nh + o0) = __halves2bfloat162(h0, h1);
            *(__nv_bfloat162*)(nl + o0) = __halves2bfloat162(l0, l1);
            split_bf16(t2, h0, l0); split_bf16(t3, h1, l1);
            size_t o1 = (size_t)(gr + 8) * U_ + gc;
            *(__nv_bfloat162*)(nh + o1) = __halves2bfloat162(h0, h1);
            *(__nv_bfloat162*)(nl + o1) = __halves2bfloat162(l0, l1);
        }
    }
}

// out[row] = h_last[row, :] @ Wo + bo
__global__ void final_proj_kernel(const float* __restrict__ Wo,
                                  const float* __restrict__ bo,
                                  float* __restrict__ out)
{
    const __nv_bfloat16* hh = g_h_hi[0];   // T_=80 even -> final state in buffer 0
    const __nv_bfloat16* hl = g_h_lo[0];
    int row = blockIdx.x;
    int tid = threadIdx.x;     // 128 threads
    float s = 0.0f;
    size_t base = (size_t)row * U_;
#pragma unroll 4
    for (int i = tid; i < U_; i += 128) {
        float hv = __bfloat162float(hh[base + i]) + __bfloat162float(hl[base + i]);
        s += hv * Wo[i];
    }
#pragma unroll
    for (int o = 16; o > 0; o >>= 1) s += __shfl_down_sync(0xffffffffu, s, o);
    __shared__ float red[4];
    if ((tid & 31) == 0) red[tid >> 5] = s;
    __syncthreads();
    if (tid == 0) out[row] = red[0] + red[1] + red[2] + red[3] + bo[0];
}

extern "C" void kernel_launch(void* const* d_in, const int* in_sizes, int n_in,
                              void* d_out, int out_size)
{
    const int*   inputs = (const int*)  d_in[0];
    const float* emb    = (const float*)d_in[1];
    const float* Wx     = (const float*)d_in[2];
    const float* Wh     = (const float*)d_in[3];
    const float* b      = (const float*)d_in[4];
    const float* Wo     = (const float*)d_in[5];
    const float* bo     = (const float*)d_in[6];
    float* out = (float*)d_out;

    cudaFuncSetAttribute(rnn_step_bf16, cudaFuncAttributeMaxDynamicSharedMemorySize,
                         SMEM_TOTAL);

    // Prep: split/transposed/padded bf16 weights + embedding, h0 = 0
    prep_bt_kernel<<<(U_ * KTOT + 255) / 256, 256>>>(Wh, Wx);
    prep_emb_kernel<<<(V_ * EPAD + 255) / 256, 256>>>(emb);
    {
        size_t n = (size_t)B_ * U_;
        zero_h_kernel<<<(int)((n + 255) / 256), 256>>>();
    }

    // 80 recurrence steps (ping-pong hi/lo planes)
    dim3 grid(U_ / NT, B_ / MT);
    for (int t = 0; t < T_; t++) {
        rnn_step_bf16<<<grid, NTHREADS, SMEM_TOTAL>>>(inputs, b, t);
    }

    final_proj_kernel<<<B_, 128>>>(Wo, bo, out);
}

// round 13
// speedup vs baseline: 1.0708x; 1.0314x over previous
#include <cuda_runtime.h>
#include <cuda_bf16.h>
#include <cstdint>
#include <cstddef>

#define B_ 4096
#define T_ 80
#define V_ 10000
#define E_ 100
#define U_ 1024

#define KTOT 1152            // 1024 (Wh) + 128 (Wx padded from 100)
#define EPAD 128             // padded embedding width
#define NCHUNK 36            // 4 emb chunks first, then 32 Wh chunks
#define MT 128
#define NT 128
#define KC 32
#define NSTAGE 2
#define NTHREADS 128
#define LDAB 40              // row stride in bf16 elements (80 B): conflict-free ldmatrix

// byte sizes
#define ROWB (LDAB * 2)                  // 80 B per row
#define A_PLANE_B (MT * ROWB)            // 10240
#define A_STAGE_B (2 * A_PLANE_B)        // 20480 (hi + lo)
#define B_PLANE_B (NT * ROWB)            // 10240
#define B_STAGE_B (2 * B_PLANE_B)        // 20480
#define SM_A_OFF   0
#define SM_B_OFF   (NSTAGE * A_STAGE_B)                 // 40960
#define SM_IDX_OFF (SM_B_OFF + NSTAGE * B_STAGE_B)      // 81920, 2 slots x 128 ints
#define SMEM_TOTAL (SM_IDX_OFF + 2 * MT * 4)            // 82944

// ---- device scratch (allocation-free) ----
__device__ __align__(256) __nv_bfloat16 g_h_hi[2][(size_t)B_ * U_];
__device__ __align__(256) __nv_bfloat16 g_h_lo[2][(size_t)B_ * U_];
__device__ __align__(256) __nv_bfloat16 g_Bth[(size_t)U_ * KTOT];   // [n][k] hi
__device__ __align__(256) __nv_bfloat16 g_Btl[(size_t)U_ * KTOT];   // [n][k] lo
__device__ __align__(256) __nv_bfloat16 g_emb_hi[(size_t)V_ * EPAD];
__device__ __align__(256) __nv_bfloat16 g_emb_lo[(size_t)V_ * EPAD];
__device__ unsigned int g_bar[B_ / MT];   // per-m-group step counters (32)

static __device__ __forceinline__ uint32_t smem_u32(const void* p) {
    uint32_t a;
    asm("{ .reg .u64 t; cvta.to.shared.u64 t, %1; cvt.u32.u64 %0, t; }" : "=r"(a) : "l"(p));
    return a;
}
static __device__ __forceinline__ void cp_async16(uint32_t s, const void* g) {
    asm volatile("cp.async.cg.shared.global [%0], [%1], 16;" :: "r"(s), "l"(g));
}
static __device__ __forceinline__ void split_bf16(float v, __nv_bfloat16& hi, __nv_bfloat16& lo) {
    hi = __float2bfloat16(v);
    lo = __float2bfloat16(v - __bfloat162float(hi));
}
static __device__ __forceinline__ void ldsm4(uint32_t* r, uint32_t addr) {
    asm volatile("ldmatrix.sync.aligned.m8n8.x4.shared.b16 {%0,%1,%2,%3}, [%4];"
                 : "=r"(r[0]), "=r"(r[1]), "=r"(r[2]), "=r"(r[3]) : "r"(addr));
}
static __device__ __forceinline__ void mma_bf16(float* c, const uint32_t* a,
                                                uint32_t b0, uint32_t b1) {
    asm volatile("mma.sync.aligned.m16n8k16.row.col.f32.bf16.bf16.f32 "
                 "{%0,%1,%2,%3}, {%4,%5,%6,%7}, {%8,%9}, {%0,%1,%2,%3};"
                 : "+f"(c[0]), "+f"(c[1]), "+f"(c[2]), "+f"(c[3])
                 : "r"(a[0]), "r"(a[1]), "r"(a[2]), "r"(a[3]), "r"(b0), "r"(b1));
}
static __device__ __forceinline__ unsigned int ld_acquire_gpu(const unsigned int* p) {
    unsigned int v;
    asm volatile("ld.acquire.gpu.u32 %0, [%1];" : "=r"(v) : "l"(p) : "memory");
    return v;
}
static __device__ __forceinline__ void red_release_add(unsigned int* p, unsigned int v) {
    asm volatile("red.release.gpu.global.add.u32 [%0], %1;" :: "l"(p), "r"(v) : "memory");
}

// ---------------- prep kernels ----------------
__global__ void prep_bt_kernel(const float* __restrict__ Wh, const float* __restrict__ Wx) {
    int idx = blockIdx.x * 256 + threadIdx.x;
    if (idx >= U_ * KTOT) return;
    int n = idx / KTOT;
    int k = idx - n * KTOT;
    float v = 0.0f;
    if (k < U_)            v = Wh[(size_t)k * U_ + n];
    else if (k < U_ + E_)  v = Wx[(size_t)(k - U_) * U_ + n];
    __nv_bfloat16 hi, lo; split_bf16(v, hi, lo);
    g_Bth[idx] = hi; g_Btl[idx] = lo;
}
__global__ void prep_emb_kernel(const float* __restrict__ emb) {
    int idx = blockIdx.x * 256 + threadIdx.x;
    if (idx >= V_ * EPAD) return;
    int tok = idx >> 7;
    int k = idx & (EPAD - 1);
    float v = (k < E_) ? emb[(size_t)tok * E_ + k] : 0.0f;
    __nv_bfloat16 hi, lo; split_bf16(v, hi, lo);
    g_emb_hi[idx] = hi; g_emb_lo[idx] = lo;
}
__global__ void zero_h_kernel() {
    size_t i = (size_t)blockIdx.x * blockDim.x + threadIdx.x;
    if (i < (size_t)B_ * U_) {
        g_h_hi[0][i] = __float2bfloat16(0.0f);
        g_h_lo[0][i] = __float2bfloat16(0.0f);
    }
    if (i < B_ / MT) g_bar[i] = 0u;
}

// ---------------- persistent recurrence: all 80 steps in one kernel ----------------
// Grid (8, 32) = 256 CTAs, 128 threads, 2 CTAs/SM -> single-wave residency (<=296).
// Per-m-group gmem barrier between steps; emb chunks (h-independent) run pre-barrier;
// next step's chunks 0,1 issued under the epilogue. R9 mainloop otherwise.
__global__ __launch_bounds__(NTHREADS, 2)
void rnn_persistent(const int* __restrict__ inputs, const float* __restrict__ bvec)
{
    extern __shared__ char smem[];
    int* sIdx = (int*)(smem + SM_IDX_OFF);    // [2][MT]
    const uint32_t sbase = smem_u32(smem);

    const int tid = threadIdx.x;
    const int wid = tid >> 5;
    const int lane = tid & 31;
    const int warp_m = wid & 1;       // 2 m-tiles of 64
    const int warp_n = wid >> 1;      // 2 n-tiles of 64
    const int n0 = blockIdx.x * NT;
    const int mi = blockIdx.y;
    const int m0 = mi * MT;

    // ldmatrix lane address components
    const int a_r = lane & 15;
    const int a_c = (lane >> 4) * 16;
    const int b_r = (lane & 7) + ((lane >> 4) << 3);
    const int b_c = ((lane >> 3) & 1) * 16;
    const int er = lane >> 2;
    const int ec = (lane & 3) * 2;

    // load-index precompute for producers
    const int p_row = tid >> 2, p_sc = tid & 3;

    // B producer: weight chunk bk (0..35 in KTOT/32 units)
    auto issue_B = [&](int s, int bk) {
        const uint32_t bHiB = sbase + SM_B_OFF + (uint32_t)(s * B_STAGE_B);
        const uint32_t bLoB = bHiB + B_PLANE_B;
        const __nv_bfloat16* bh_g = g_Bth + (size_t)n0 * KTOT + bk * KC;
        const __nv_bfloat16* bl_g = g_Btl + (size_t)n0 * KTOT + bk * KC;
#pragma unroll
        for (int r = 0; r < 4; r++) {
            int row = p_row + r * 32;
            uint32_t off = (uint32_t)(row * ROWB + p_sc * 16);
            cp_async16(bHiB + off, bh_g + (size_t)row * KTOT + p_sc * 8);
            cp_async16(bLoB + off, bl_g + (size_t)row * KTOT + p_sc * 8);
        }
    };
    // emb chunk cid (0..3): A from embedding via sIdx[slot], B chunk 32+cid
    auto issue_emb = [&](int cid, int slot) {
        const int s = cid % NSTAGE;
        const uint32_t aHiB = sbase + SM_A_OFF + (uint32_t)(s * A_STAGE_B);
        const uint32_t aLoB = aHiB + A_PLANE_B;
        const int kb = cid * KC;
        const int* si = sIdx + slot * MT;
#pragma unroll
        for (int r = 0; r < 4; r++) {
            int row = p_row + r * 32;
            uint32_t off = (uint32_t)(row * ROWB + p_sc * 16);
            size_t g = (size_t)si[row] * EPAD + kb + p_sc * 8;
            cp_async16(aHiB + off, g_emb_hi + g);
            cp_async16(aLoB + off, g_emb_lo + g);
        }
        issue_B(s, 32 + cid);
        asm volatile("cp.async.commit_group;" ::: "memory");
    };

    // prime sIdx slots for t=0, t=1
    sIdx[0 * MT + tid] = inputs[(size_t)(m0 + tid) * T_ + 0];
    sIdx[1 * MT + tid] = inputs[(size_t)(m0 + tid) * T_ + 1];
    __syncthreads();
    issue_emb(0, 0); issue_emb(1, 0);

    for (int t = 0; t < T_; t++) {
        const int cur = t & 1;
        const __nv_bfloat16* __restrict__ hh_g = g_h_hi[t & 1];
        const __nv_bfloat16* __restrict__ hl_g = g_h_lo[t & 1];
        __nv_bfloat16* __restrict__ nh = g_h_hi[(t & 1) ^ 1];
        __nv_bfloat16* __restrict__ nl = g_h_lo[(t & 1) ^ 1];

        // Wh chunk cid (4..35): A from h planes, B chunk cid-4
        auto issue_wh = [&](int cid) {
            const int s = cid % NSTAGE;
            const int kc = cid - 4;
            const uint32_t aHiB = sbase + SM_A_OFF + (uint32_t)(s * A_STAGE_B);
            const uint32_t aLoB = aHiB + A_PLANE_B;
            const __nv_bfloat16* sh = hh_g + (size_t)m0 * U_ + kc * KC;
            const __nv_bfloat16* sl = hl_g + (size_t)m0 * U_ + kc * KC;
#pragma unroll
            for (int r = 0; r < 4; r++) {
                int row = p_row + r * 32;
                uint32_t off = (uint32_t)(row * ROWB + p_sc * 16);
                cp_async16(aHiB + off, sh + (size_t)row * U_ + p_sc * 8);
                cp_async16(aLoB + off, sl + (size_t)row * U_ + p_sc * 8);
            }
            issue_B(s, kc);
            asm volatile("cp.async.commit_group;" ::: "memory");
        };

        float acc[4][8][4];
#pragma unroll
        for (int i = 0; i < 4; i++)
#pragma unroll
            for (int j = 0; j < 8; j++)
#pragma unroll
                for (int e = 0; e < 4; e++) acc[i][j][e] = 0.0f;

        for (int c = 0; c < NCHUNK; c++) {
            if (c < NCHUNK - 1) asm volatile("cp.async.wait_group 1;" ::: "memory");
            else                asm volatile("cp.async.wait_group 0;" ::: "memory");
            __syncthreads();

            const int s = c % NSTAGE;
            const uint32_t aBase = sbase + SM_A_OFF + (uint32_t)(s * A_STAGE_B)
                                 + (uint32_t)(warp_m * 64 * ROWB);
            const uint32_t bBase = sbase + SM_B_OFF + (uint32_t)(s * B_STAGE_B)
                                 + (uint32_t)(warp_n * 64 * ROWB);

#pragma unroll
            for (int k16 = 0; k16 < 2; k16++) {
                uint32_t bh[4][4], bl[4][4];
#pragma unroll
                for (int jj = 0; jj < 4; jj++) {
                    uint32_t baddr = bBase + (uint32_t)((jj * 16 + b_r) * ROWB + k16 * 32 + b_c);
                    ldsm4(bh[jj], baddr);
                    ldsm4(bl[jj], baddr + B_PLANE_B);
                }
                uint32_t ah[2][4], al[2][4];
                {
                    uint32_t addr = aBase + (uint32_t)((a_r) * ROWB + k16 * 32 + a_c);
                    ldsm4(ah[0], addr);
                    ldsm4(al[0], addr + A_PLANE_B);
                }
#pragma unroll
                for (int i = 0; i < 4; i++) {
                    const int curb = i & 1;
                    if (i < 3) {
                        uint32_t addr = aBase + (uint32_t)(((i + 1) * 16 + a_r) * ROWB + k16 * 32 + a_c);
                        ldsm4(ah[curb ^ 1], addr);
                        ldsm4(al[curb ^ 1], addr + A_PLANE_B);
                    }
#pragma unroll
                    for (int jj = 0; jj < 4; jj++) {
                        mma_bf16(acc[i][2 * jj],     ah[curb], bh[jj][0], bh[jj][1]);
                        mma_bf16(acc[i][2 * jj],     al[curb], bh[jj][0], bh[jj][1]);
                        mma_bf16(acc[i][2 * jj],     ah[curb], bl[jj][0], bl[jj][1]);
                        mma_bf16(acc[i][2 * jj + 1], ah[curb], bh[jj][2], bh[jj][3]);
                        mma_bf16(acc[i][2 * jj + 1], al[curb], bh[jj][2], bh[jj][3]);
                        mma_bf16(acc[i][2 * jj + 1], ah[curb], bl[jj][2], bl[jj][3]);
                    }
                }
            }
            __syncthreads();
            if (c + NSTAGE < NCHUNK) {
                int nc = c + NSTAGE;
                if (nc < 4) issue_emb(nc, cur);
                else {
                    if (nc == 4) {
                        // group barrier: all 8 producers of rows [m0, m0+128) done step t-1
                        const unsigned int need = 8u * (unsigned int)t;
                        while (ld_acquire_gpu(&g_bar[mi]) < need) __nanosleep(64);
                    }
                    issue_wh(nc);
                }
            }
        }

        // Overlap next step's h-independent loads with the epilogue
        if (t + 1 < T_) { issue_emb(0, (t + 1) & 1); issue_emb(1, (t + 1) & 1); }

        // ---- epilogue: bias + tanh + bf16 hi/lo split + direct store ----
#pragma unroll
        for (int j = 0; j < 8; j++) {
            int gc = n0 + warp_n * 64 + j * 8 + ec;
            float bia0 = bvec[gc], bia1 = bvec[gc + 1];
#pragma unroll
            for (int i = 0; i < 4; i++) {
                int gr = m0 + warp_m * 64 + i * 16 + er;
                float t0 = tanhf(acc[i][j][0] + bia0);
                float t1 = tanhf(acc[i][j][1] + bia1);
                float t2 = tanhf(acc[i][j][2] + bia0);
                float t3 = tanhf(acc[i][j][3] + bia1);
                __nv_bfloat16 h0, l0, h1, l1;
                split_bf16(t0, h0, l0); split_bf16(t1, h1, l1);
                size_t o0 = (size_t)gr * U_ + gc;
                *(__nv_bfloat162*)(nh + o0) = __halves2bfloat162(h0, h1);
                *(__nv_bfloat162*)(nl + o0) = __halves2bfloat162(l0, l1);
                split_bf16(t2, h0, l0); split_bf16(t3, h1, l1);
                size_t o1 = (size_t)(gr + 8) * U_ + gc;
                *(__nv_bfloat162*)(nh + o1) = __halves2bfloat162(h0, h1);
                *(__nv_bfloat162*)(nl + o1) = __halves2bfloat162(l0, l1);
            }
        }

        __threadfence();
        if (t + 2 < T_) sIdx[cur * MT + tid] = inputs[(size_t)(m0 + tid) * T_ + (t + 2)];
        __syncthreads();
        if (t + 1 < T_ && tid == 0) red_release_add(&g_bar[mi], 1u);
    }
}

// out[row] = h_last[row, :] @ Wo + bo
__global__ void final_proj_kernel(const float* __restrict__ Wo,
                                  const float* __restrict__ bo,
                                  float* __restrict__ out)
{
    const __nv_bfloat16* hh = g_h_hi[0];   // T_=80 even -> final state in buffer 0
    const __nv_bfloat16* hl = g_h_lo[0];
    int row = blockIdx.x;
    int tid = threadIdx.x;     // 128 threads
    float s = 0.0f;
    size_t base = (size_t)row * U_;
#pragma unroll 4
    for (int i = tid; i < U_; i += 128) {
        float hv = __bfloat162float(hh[base + i]) + __bfloat162float(hl[base + i]);
        s += hv * Wo[i];
    }
#pragma unroll
    for (int o = 16; o > 0; o >>= 1) s += __shfl_down_sync(0xffffffffu, s, o);
    __shared__ float red[4];
    if ((tid & 31) == 0) red[tid >> 5] = s;
    __syncthreads();
    if (tid == 0) out[row] = red[0] + red[1] + red[2] + red[3] + bo[0];
}

extern "C" void kernel_launch(void* const* d_in, const int* in_sizes, int n_in,
                              void* d_out, int out_size)
{
    const int*   inputs = (const int*)  d_in[0];
    const float* emb    = (const float*)d_in[1];
    const float* Wx     = (const float*)d_in[2];
    const float* Wh     = (const float*)d_in[3];
    const float* b      = (const float*)d_in[4];
    const float* Wo     = (const float*)d_in[5];
    const float* bo     = (const float*)d_in[6];
    float* out = (float*)d_out;

    cudaFuncSetAttribute(rnn_persistent, cudaFuncAttributeMaxDynamicSharedMemorySize,
                         SMEM_TOTAL);

    // Prep: split/transposed/padded bf16 weights + embedding, h0 = 0, barriers = 0
    prep_bt_kernel<<<(U_ * KTOT + 255) / 256, 256>>>(Wh, Wx);
    prep_emb_kernel<<<(V_ * EPAD + 255) / 256, 256>>>(emb);
    {
        size_t n = (size_t)B_ * U_;
        zero_h_kernel<<<(int)((n + 255) / 256), 256>>>();
    }

    // All 80 recurrence steps in one persistent kernel
    dim3 grid(U_ / NT, B_ / MT);
    rnn_persistent<<<grid, NTHREADS, SMEM_TOTAL>>>(inputs, b);

    final_proj_kernel<<<B_, 128>>>(Wo, bo, out);
}

// round 14
// speedup vs baseline: 1.2491x; 1.1664x over previous
#include <cuda_runtime.h>
#include <cuda_bf16.h>
#include <cstdint>
#include <cstddef>

#define B_ 4096
#define T_ 80
#define V_ 10000
#define E_ 100
#define U_ 1024

#define KTOT 1152            // 1024 (Wh) + 128 (Wx padded from 100)
#define EPAD 128             // padded embedding width
#define NCHUNK 36            // KTOT / 32
#define MT 128
#define NT 128
#define KC 32
#define NSTAGE 3
#define NTHREADS 128
#define LDAB 40              // A row stride in bf16 (80 B): conflict-free ldmatrix

#define ROWB (LDAB * 2)                  // 80 B per row
#define A_PLANE_B (MT * ROWB)            // 10240
#define A_STAGE_B (2 * A_PLANE_B)        // 20480 (hi + lo)
#define SM_A_OFF   0
#define SM_IDX_OFF (NSTAGE * A_STAGE_B)  // 61440
#define SMEM_TOTAL (SM_IDX_OFF + MT * 4) // 61952

#define NBK2 (2 * NCHUNK)                // 72 k16-blocks
#define NSLAB (U_ / 16)                  // 64 n-slabs of 16

// ---- device scratch (allocation-free) ----
__device__ __align__(256) __nv_bfloat16 g_h_hi[2][(size_t)B_ * U_];
__device__ __align__(256) __nv_bfloat16 g_h_lo[2][(size_t)B_ * U_];
__device__ __align__(256) uint4 g_Bfh[(size_t)NBK2 * NSLAB * 32];   // B frags hi
__device__ __align__(256) uint4 g_Bfl[(size_t)NBK2 * NSLAB * 32];   // B frags lo
__device__ __align__(256) __nv_bfloat16 g_emb_hi[(size_t)V_ * EPAD];
__device__ __align__(256) __nv_bfloat16 g_emb_lo[(size_t)V_ * EPAD];

static __device__ __forceinline__ uint32_t smem_u32(const void* p) {
    uint32_t a;
    asm("{ .reg .u64 t; cvta.to.shared.u64 t, %1; cvt.u32.u64 %0, t; }" : "=r"(a) : "l"(p));
    return a;
}
static __device__ __forceinline__ void cp_async16(uint32_t s, const void* g) {
    asm volatile("cp.async.cg.shared.global [%0], [%1], 16;" :: "r"(s), "l"(g));
}
static __device__ __forceinline__ void split_bf16(float v, __nv_bfloat16& hi, __nv_bfloat16& lo) {
    hi = __float2bfloat16(v);
    lo = __float2bfloat16(v - __bfloat162float(hi));
}
static __device__ __forceinline__ void ldsm4(uint32_t* r, uint32_t addr) {
    asm volatile("ldmatrix.sync.aligned.m8n8.x4.shared.b16 {%0,%1,%2,%3}, [%4];"
                 : "=r"(r[0]), "=r"(r[1]), "=r"(r[2]), "=r"(r[3]) : "r"(addr));
}
static __device__ __forceinline__ void mma_bf16(float* c, const uint32_t* a,
                                                uint32_t b0, uint32_t b1) {
    asm volatile("mma.sync.aligned.m16n8k16.row.col.f32.bf16.bf16.f32 "
                 "{%0,%1,%2,%3}, {%4,%5,%6,%7}, {%8,%9}, {%0,%1,%2,%3};"
                 : "+f"(c[0]), "+f"(c[1]), "+f"(c[2]), "+f"(c[3])
                 : "r"(a[0]), "r"(a[1]), "r"(a[2]), "r"(a[3]), "r"(b0), "r"(b1));
}

// ---------------- prep kernels ----------------
// Pre-swizzle B = [Wh^T ; Wx^T ; 0] into exact m16n8k16 B-fragment layout.
// Block (bk2, nslab): 32 lanes x uint4. reg r: n = nslab*16 + ((r>>1)&1)*8 + lane/4,
// k = bk2_kbase + (r&1)*8 + (lane%4)*2, packing bf16(k),bf16(k+1).
__global__ void prep_bf_kernel(const float* __restrict__ Wh, const float* __restrict__ Wx) {
    int idx = blockIdx.x * 256 + threadIdx.x;
    if (idx >= NBK2 * NSLAB * 32) return;
    int lane = idx & 31;
    int nslab = (idx >> 5) & (NSLAB - 1);
    int bk2 = idx >> 11;
    int kbase = (bk2 >> 1) * 32 + (bk2 & 1) * 16;
    uint32_t rh[4], rl[4];
#pragma unroll
    for (int r = 0; r < 4; r++) {
        int n = nslab * 16 + ((r >> 1) & 1) * 8 + (lane >> 2);
        int k = kbase + (r & 1) * 8 + (lane & 3) * 2;
        float v0 = 0.0f, v1 = 0.0f;
        if (k < U_)            v0 = Wh[(size_t)k * U_ + n];
        else if (k < U_ + E_)  v0 = Wx[(size_t)(k - U_) * U_ + n];
        int k1 = k + 1;
        if (k1 < U_)           v1 = Wh[(size_t)k1 * U_ + n];
        else if (k1 < U_ + E_) v1 = Wx[(size_t)(k1 - U_) * U_ + n];
        __nv_bfloat16 h0, l0, h1, l1;
        split_bf16(v0, h0, l0);
        split_bf16(v1, h1, l1);
        __nv_bfloat162 ph = __halves2bfloat162(h0, h1);
        __nv_bfloat162 pl = __halves2bfloat162(l0, l1);
        rh[r] = *(uint32_t*)&ph;
        rl[r] = *(uint32_t*)&pl;
    }
    g_Bfh[idx] = make_uint4(rh[0], rh[1], rh[2], rh[3]);
    g_Bfl[idx] = make_uint4(rl[0], rl[1], rl[2], rl[3]);
}
__global__ void prep_emb_kernel(const float* __restrict__ emb) {
    int idx = blockIdx.x * 256 + threadIdx.x;
    if (idx >= V_ * EPAD) return;
    int tok = idx >> 7;
    int k = idx & (EPAD - 1);
    float v = (k < E_) ? emb[(size_t)tok * E_ + k] : 0.0f;
    __nv_bfloat16 hi, lo; split_bf16(v, hi, lo);
    g_emb_hi[idx] = hi; g_emb_lo[idx] = lo;
}
__global__ void zero_h_kernel() {
    size_t i = (size_t)blockIdx.x * blockDim.x + threadIdx.x;
    if (i < (size_t)B_ * U_) {
        g_h_hi[0][i] = __float2bfloat16(0.0f);
        g_h_lo[0][i] = __float2bfloat16(0.0f);
    }
}

// ---------------- recurrence step ----------------
// Grid (8, 32) = 256 CTAs, 128 threads (4 warps, 2x2 -> 64x64 tiles), 2 CTAs/SM.
// A: cp.async 3-stage SMEM pipeline (ONE barrier per chunk).
// B: preformatted fragments via LDG.128 from L2, register double-buffered (X/Y).
__global__ __launch_bounds__(NTHREADS, 2)
void rnn_step_bf16(const int* __restrict__ inputs, const float* __restrict__ bvec, int t)
{
    extern __shared__ char smem[];
    int* sIdx = (int*)(smem + SM_IDX_OFF);
    const uint32_t sbase = smem_u32(smem);

    const int tid = threadIdx.x;
    const int wid = tid >> 5;
    const int lane = tid & 31;
    const int warp_m = wid & 1;
    const int warp_n = wid >> 1;
    const int n0 = blockIdx.x * NT;
    const int m0 = blockIdx.y * MT;

    const __nv_bfloat16* __restrict__ hh_g = g_h_hi[t & 1];
    const __nv_bfloat16* __restrict__ hl_g = g_h_lo[t & 1];
    __nv_bfloat16* __restrict__ nh = g_h_hi[(t & 1) ^ 1];
    __nv_bfloat16* __restrict__ nl = g_h_lo[(t & 1) ^ 1];

    sIdx[tid] = inputs[(size_t)(m0 + tid) * T_ + t];
    __syncthreads();

    float acc[4][8][4];
#pragma unroll
    for (int i = 0; i < 4; i++)
#pragma unroll
        for (int j = 0; j < 8; j++)
#pragma unroll
            for (int e = 0; e < 4; e++) acc[i][j][e] = 0.0f;

    const int a_r = lane & 15;
    const int a_c = (lane >> 4) * 16;
    const int p_row = tid >> 2, p_sc = tid & 3;

    // A producer (hi+lo planes), 8 cp.async/thread + commit
    auto issue_A = [&](int c) {
        const int s = c % NSTAGE;
        const uint32_t aHiB = sbase + SM_A_OFF + (uint32_t)(s * A_STAGE_B);
        const uint32_t aLoB = aHiB + A_PLANE_B;
        if (c < 32) {
            const __nv_bfloat16* sh = hh_g + (size_t)m0 * U_ + c * KC;
            const __nv_bfloat16* sl = hl_g + (size_t)m0 * U_ + c * KC;
#pragma unroll
            for (int r = 0; r < 4; r++) {
                int row = p_row + r * 32;
                uint32_t off = (uint32_t)(row * ROWB + p_sc * 16);
                cp_async16(aHiB + off, sh + (size_t)row * U_ + p_sc * 8);
                cp_async16(aLoB + off, sl + (size_t)row * U_ + p_sc * 8);
            }
        } else {
            const int kb = (c - 32) * KC;
#pragma unroll
            for (int r = 0; r < 4; r++) {
                int row = p_row + r * 32;
                uint32_t off = (uint32_t)(row * ROWB + p_sc * 16);
                size_t g = (size_t)sIdx[row] * EPAD + kb + p_sc * 8;
                cp_async16(aHiB + off, g_emb_hi + g);
                cp_async16(aLoB + off, g_emb_lo + g);
            }
        }
        asm volatile("cp.async.commit_group;" ::: "memory");
    };

    // B fragment pointers (this CTA+warp's 4 n-slabs start at nslab0)
    const size_t fboff = (size_t)(blockIdx.x * 8 + warp_n * 4) * 32 + lane;
    const uint4* __restrict__ Bfh = g_Bfh + fboff;
    const uint4* __restrict__ Bfl = g_Bfl + fboff;

    uint32_t Xh[4][4], Xl[4][4], Yh[4][4], Yl[4][4];
    auto loadB = [&](uint32_t (&bh)[4][4], uint32_t (&bl)[4][4], int bk2) {
        size_t base = (size_t)bk2 * (NSLAB * 32);
#pragma unroll
        for (int jj = 0; jj < 4; jj++) {
            uint4 vh = __ldg(Bfh + base + jj * 32);
            uint4 vl = __ldg(Bfl + base + jj * 32);
            bh[jj][0] = vh.x; bh[jj][1] = vh.y; bh[jj][2] = vh.z; bh[jj][3] = vh.w;
            bl[jj][0] = vl.x; bl[jj][1] = vl.y; bl[jj][2] = vl.z; bl[jj][3] = vl.w;
        }
    };

    auto computeK16 = [&](uint32_t aBase, int k16,
                          uint32_t (&bh)[4][4], uint32_t (&bl)[4][4]) {
        uint32_t ah[2][4], al[2][4];
        {
            uint32_t addr = aBase + (uint32_t)(a_r * ROWB + k16 * 32 + a_c);
            ldsm4(ah[0], addr);
            ldsm4(al[0], addr + A_PLANE_B);
        }
#pragma unroll
        for (int i = 0; i < 4; i++) {
            const int cur = i & 1;
            if (i < 3) {
                uint32_t addr = aBase + (uint32_t)(((i + 1) * 16 + a_r) * ROWB + k16 * 32 + a_c);
                ldsm4(ah[cur ^ 1], addr);
                ldsm4(al[cur ^ 1], addr + A_PLANE_B);
            }
#pragma unroll
            for (int jj = 0; jj < 4; jj++) {
                mma_bf16(acc[i][2 * jj],     ah[cur], bh[jj][0], bh[jj][1]);
                mma_bf16(acc[i][2 * jj],     al[cur], bh[jj][0], bh[jj][1]);
                mma_bf16(acc[i][2 * jj],     ah[cur], bl[jj][0], bl[jj][1]);
                mma_bf16(acc[i][2 * jj + 1], ah[cur], bh[jj][2], bh[jj][3]);
                mma_bf16(acc[i][2 * jj + 1], al[cur], bh[jj][2], bh[jj][3]);
                mma_bf16(acc[i][2 * jj + 1], ah[cur], bl[jj][2], bl[jj][3]);
            }
        }
    };

    issue_A(0); issue_A(1);
    loadB(Xh, Xl, 0);

    for (int c = 0; c < NCHUNK; c++) {
        if (c < NCHUNK - 1) asm volatile("cp.async.wait_group 1;" ::: "memory");
        else                asm volatile("cp.async.wait_group 0;" ::: "memory");
        __syncthreads();   // single barrier: stage (c-1)%3 now free, stage c%3 visible
        if (c + 2 < NCHUNK) issue_A(c + 2);   // writes stage (c+2)%3 == (c-1)%3

        const uint32_t aBase = sbase + (uint32_t)((c % NSTAGE) * A_STAGE_B)
                             + (uint32_t)(warp_m * 64 * ROWB);

        // k16 = 0: prefetch Y (this chunk's second block), compute with X
        loadB(Yh, Yl, 2 * c + 1);
        computeK16(aBase, 0, Xh, Xl);
        // k16 = 1: prefetch X (next chunk's first block), compute with Y
        int nbk2 = 2 * c + 2; if (nbk2 > NBK2 - 1) nbk2 = NBK2 - 1;
        loadB(Xh, Xl, nbk2);
        computeK16(aBase, 1, Yh, Yl);
    }

    // ---- epilogue: bias + tanh + bf16 hi/lo split + direct store ----
    const int er = lane >> 2;
    const int ec = (lane & 3) * 2;
#pragma unroll
    for (int j = 0; j < 8; j++) {
        int gc = n0 + warp_n * 64 + j * 8 + ec;
        float bia0 = bvec[gc], bia1 = bvec[gc + 1];
#pragma unroll
        for (int i = 0; i < 4; i++) {
            int gr = m0 + warp_m * 64 + i * 16 + er;
            float t0 = tanhf(acc[i][j][0] + bia0);
            float t1 = tanhf(acc[i][j][1] + bia1);
            float t2 = tanhf(acc[i][j][2] + bia0);
            float t3 = tanhf(acc[i][j][3] + bia1);
            __nv_bfloat16 h0, l0, h1, l1;
            split_bf16(t0, h0, l0); split_bf16(t1, h1, l1);
            size_t o0 = (size_t)gr * U_ + gc;
            *(__nv_bfloat162*)(nh + o0) = __halves2bfloat162(h0, h1);
            *(__nv_bfloat162*)(nl + o0) = __halves2bfloat162(l0, l1);
            split_bf16(t2, h0, l0); split_bf16(t3, h1, l1);
            size_t o1 = (size_t)(gr + 8) * U_ + gc;
            *(__nv_bfloat162*)(nh + o1) = __halves2bfloat162(h0, h1);
            *(__nv_bfloat162*)(nl + o1) = __halves2bfloat162(l0, l1);
        }
    }
}

// out[row] = h_last[row, :] @ Wo + bo
__global__ void final_proj_kernel(const float* __restrict__ Wo,
                                  const float* __restrict__ bo,
                                  float* __restrict__ out)
{
    const __nv_bfloat16* hh = g_h_hi[0];   // T_=80 even -> final state in buffer 0
    const __nv_bfloat16* hl = g_h_lo[0];
    int row = blockIdx.x;
    int tid = threadIdx.x;     // 128 threads
    float s = 0.0f;
    size_t base = (size_t)row * U_;
#pragma unroll 4
    for (int i = tid; i < U_; i += 128) {
        float hv = __bfloat162float(hh[base + i]) + __bfloat162float(hl[base + i]);
        s += hv * Wo[i];
    }
#pragma unroll
    for (int o = 16; o > 0; o >>= 1) s += __shfl_down_sync(0xffffffffu, s, o);
    __shared__ float red[4];
    if ((tid & 31) == 0) red[tid >> 5] = s;
    __syncthreads();
    if (tid == 0) out[row] = red[0] + red[1] + red[2] + red[3] + bo[0];
}

extern "C" void kernel_launch(void* const* d_in, const int* in_sizes, int n_in,
                              void* d_out, int out_size)
{
    const int*   inputs = (const int*)  d_in[0];
    const float* emb    = (const float*)d_in[1];
    const float* Wx     = (const float*)d_in[2];
    const float* Wh     = (const float*)d_in[3];
    const float* b      = (const float*)d_in[4];
    const float* Wo     = (const float*)d_in[5];
    const float* bo     = (const float*)d_in[6];
    float* out = (float*)d_out;

    cudaFuncSetAttribute(rnn_step_bf16, cudaFuncAttributeMaxDynamicSharedMemorySize,
                         SMEM_TOTAL);

    // Prep: fragment-form bf16 weights, split embedding, h0 = 0
    prep_bf_kernel<<<(NBK2 * NSLAB * 32 + 255) / 256, 256>>>(Wh, Wx);
    prep_emb_kernel<<<(V_ * EPAD + 255) / 256, 256>>>(emb);
    {
        size_t n = (size_t)B_ * U_;
        zero_h_kernel<<<(int)((n + 255) / 256), 256>>>();
    }

    // 80 recurrence steps (ping-pong hi/lo planes)
    dim3 grid(U_ / NT, B_ / MT);
    for (int t = 0; t < T_; t++) {
        rnn_step_bf16<<<grid, NTHREADS, SMEM_TOTAL>>>(inputs, b, t);
    }

    final_proj_kernel<<<B_, 128>>>(Wo, bo, out);
}